// round 9
// baseline (speedup 1.0000x reference)
#include <cuda_runtime.h>
#include <cstddef>

#define Bz 8
#define Tz 256
#define Uz 64
#define U1 65
#define CSTRIDE 66    // paired-row stride in float2 (528 B = 33*16 -> aligned rows)
#define Vz 512
#define ND  320       // diagonal rows: s in [0, 319]
#define NDC (ND * CSTRIDE)   // 21120 float2 per batch
#define NEG 1e30f

#define LOG2E 1.4426950408889634f
#define LN2   0.6931471805599453f

// Scratch (device globals: allocation inside kernel_launch is forbidden)
// Paired diagonal layout: slot (s,c) = { blank2[s-c][c] , emit2[s-c+1][c-1] },
// i.e. exactly the two operands consumed by dp step d = s+1 at column c.
// Identity padding (x=0, y=-1e30) is written by lse_kernel's spare lanes.
__device__ __align__(16) float2 g_pd[Bz * NDC];
__device__ float    g_fb[Bz * U1];      // true blank2[t_last][u] (for final loss)
__device__ float    g_e0[Bz * Uz];      // true emit2[0][u] (row-0 cumsum)
__device__ float    g_loss[Bz];
__device__ unsigned g_done = 0;

__device__ __forceinline__ float ex2f(float x) {
    float r; asm("ex2.approx.ftz.f32 %0, %1;" : "=f"(r) : "f"(x)); return r;
}

// logaddexp in log2 domain: max(x,y) + log2(1 + 2^-|x-y|), Estrin poly.
// Exact at z=0 -> logadd2(x, -1e30) == x (identity), which the padding relies on.
__device__ __forceinline__ float logadd2(float x, float y)
{
    const float m  = fmaxf(x, y);
    const float z  = ex2f(-fabsf(x - y));
    const float z2 = z * z;
    const float t1 = fmaf(-0.6701403f, z, 1.4362632f);
    const float t2 = fmaf(-0.0791604f, z, 0.3126861f);
    const float p  = fmaf(z2, t2, t1);
    return fmaf(z, p, m);
}

// ---------------------------------------------------------------------------
// Kernel 1: per-row logsumexp over V=512 (one warp per (b,t,u) row, HBM-bound).
// Writes blank/emit directly into the paired diagonal layout, with length
// masking baked in, AND writes the identity padding from spare rows — no
// separate init kernel. Every slot component is written exactly once.
// ---------------------------------------------------------------------------
__global__ void __launch_bounds__(256) lse_kernel(const float* __restrict__ pred,
                                                  const int* __restrict__ target,
                                                  const int* __restrict__ pred_len)
{
    const int warp = (blockIdx.x * blockDim.x + threadIdx.x) >> 5;
    const int lane = threadIdx.x & 31;
    const int n_rows = Bz * Tz * U1;
    if (warp >= n_rows) return;

    const float* row = pred + (size_t)warp * Vz;

    float4 v[4];
    float mx = -1e30f;
#pragma unroll
    for (int c = 0; c < 4; c++) {
        v[c] = __ldcs(reinterpret_cast<const float4*>(row + c * 128 + lane * 4));
        mx = fmaxf(mx, fmaxf(fmaxf(v[c].x, v[c].y), fmaxf(v[c].z, v[c].w)));
    }
#pragma unroll
    for (int o = 16; o > 0; o >>= 1)
        mx = fmaxf(mx, __shfl_xor_sync(0xFFFFFFFFu, mx, o));

    float s = 0.0f;
#pragma unroll
    for (int c = 0; c < 4; c++) {
        s += __expf(v[c].x - mx) + __expf(v[c].y - mx)
           + __expf(v[c].z - mx) + __expf(v[c].w - mx);
    }
#pragma unroll
    for (int o = 16; o > 0; o >>= 1)
        s += __shfl_xor_sync(0xFFFFFFFFu, s, o);

    const float lse = mx + __logf(s);

    if (lane == 0) {
        const int b   = warp / (Tz * U1);
        const int r   = warp % (Tz * U1);       // per-batch row id, 0..16639
        const int t   = r / U1;
        const int u   = r % U1;
        const int plen   = pred_len[b];
        const int t_last = plen - 1;
        float2* pd = g_pd + b * NDC;

        // ---- valid writes ----
        const float vb = (row[0] - lse) * LOG2E;              // blank_id = 0
        // dp consumes blank[t-1] only for updates at t <= t_last; freeze after.
        pd[(t + u) * CSTRIDE + u].x = (t >= t_last) ? 0.0f : vb;
        if (t == t_last) g_fb[b * U1 + u] = vb;               // true value for loss

        if (u < Uz) {
            const int tgt = target[b * Uz + u];
            const float ve = (row[tgt] - lse) * LOG2E;
            // emit (t,u0) -> slot (t+u0, u0+1).y ; mask t<1 or t>t_last.
            pd[(t + u) * CSTRIDE + (u + 1)].y =
                (t < 1 || t >= plen) ? -NEG : ve;
            if (t == 0) g_e0[b * Uz + u] = ve;                // row-0 cumsum input
        }

        // ---- identity padding (spare work, hidden under DRAM stream) ----
        if (r < 4160) {
            // blank padding: column up, invalid diagonals d<up and d>255+up
            const int up = r >> 6, k = r & 63;
            const int d = (k < up) ? k : 256 + k;
            pd[d * CSTRIDE + up].x = 0.0f;
        } else if (r < 8256) {
            // emit padding, cols 1..64: valid s in [c-1, 254+c]
            const int q = r - 4160;
            const int c = 1 + (q >> 6), k = q & 63;
            const int d = (k < c - 1) ? k : 256 + k;
            pd[d * CSTRIDE + c].y = -NEG;
        } else if (r < 8576) {
            // emit col 0: never valid (u=0 has no emit path) -> all 320 rows
            const int d = r - 8256;
            pd[d * CSTRIDE].y = -NEG;
        }
    }
}

// ---------------------------------------------------------------------------
// Kernel 2: alpha DP in a single warp. Lane l owns u=2l, 2l+1; u=64 uniform.
// Staging is a pure float4 memcpy of the paired array; the loop does ONE
// LDS.128 + ONE LDS.64 (broadcast) per lane per step — 319 identical,
// unguarded steps.
// ---------------------------------------------------------------------------
__global__ void __launch_bounds__(256) dp_kernel(const int* __restrict__ target_len,
                                                 float* __restrict__ out)
{
    const int b   = blockIdx.x;
    const int tid = threadIdx.x;

    extern __shared__ __align__(16) float2 s_pd[];   // NDC float2 (169 KB)

    // Stage the paired diagonal array as float4 memcpy.
    {
        const float4* gp = reinterpret_cast<const float4*>(g_pd + b * NDC);
        float4* sp = reinterpret_cast<float4*>(s_pd);
#pragma unroll 4
        for (int i = tid; i < NDC / 2; i += 256)     // NDC/2 float4 = 10560
            sp[i] = gp[i];
    }
    __syncthreads();

    if (tid >= 32) return;       // single-warp wavefront
    const int lane = tid;
    const unsigned FULL = 0xFFFFFFFFu;
    const int tlen = target_len[b];   // [56, 64]

    // ---- Row 0 init via warp-scan cumsum of emit[0][.] ----
    const float e0a = __ldg(&g_e0[b * Uz + 2 * lane]);
    const float e0b = __ldg(&g_e0[b * Uz + 2 * lane + 1]);
    const float pair = e0a + e0b;
    float scan = pair;
#pragma unroll
    for (int o = 1; o < 32; o <<= 1) {
        const float n = __shfl_up_sync(FULL, scan, o);
        scan += (lane >= o) ? n : 0.0f;
    }
    float A_e = scan - pair;                   // alpha[0][2l]
    float A_o = A_e + e0a;                     // alpha[0][2l+1]
    float A_t = __shfl_sync(FULL, scan, 31);   // alpha[0][64], uniform

    // ---- Main loop: 319 identical, unguarded steps ----
    // Step d reads paired row s = d-1: slot (s,c) = {blank-op, emit-op} for col c.
    const float2* rp = s_pd + 2 * lane;        // this lane's pair base (cols 2l,2l+1)
    const float2* tp = s_pd + Uz;              // col-64 broadcast base
#pragma unroll 4
    for (int d = 1; d < ND; d++) {
        const float prev_o = __shfl_up_sync(FULL, A_o, 1);   // alpha[.][2l-1]
        const float o31    = __shfl_sync(FULL, A_o, 31);     // alpha[.][63]

        const float4 pv = *reinterpret_cast<const float4*>(rp);  // {b0,e0,b1,e1}
        const float2 tv = *tp;                                   // {b64,e64}

        const float xe = A_e + pv.x;
        const float ye = prev_o + pv.y;        // lane0: pv.y = -1e30 -> identity
        const float xo = A_o + pv.z;
        const float yo = A_e + pv.w;           // uses OLD A_e
        const float xt = A_t + tv.x;
        const float yt = o31 + tv.y;

        A_e = logadd2(xe, ye);
        A_o = logadd2(xo, yo);
        A_t = logadd2(xt, yt);

        rp += CSTRIDE;
        tp += CSTRIDE;
    }

    // ---- Extract alpha[t_last][tlen] (updates past t_last were frozen) ----
    const int sel = (tlen >> 1) & 31;
    const float vE = __shfl_sync(FULL, A_e, sel);
    const float vO = __shfl_sync(FULL, A_o, sel);
    const float fa = (tlen == Uz) ? A_t : ((tlen & 1) ? vO : vE);

    if (lane == 0) {
        const float fb = __ldg(&g_fb[b * U1 + tlen]);        // true blank2[t_last][tlen]
        g_loss[b] = fa + fb;                                 // log2 domain
        __threadfence();
        const unsigned n = atomicAdd(&g_done, 1);
        if (n == Bz - 1) {
            __threadfence();
            float s = 0.0f;
#pragma unroll
            for (int i = 0; i < Bz; i++)
                s += ((volatile float*)g_loss)[i];
            out[0] = -s * (LN2 / Bz);
            g_done = 0;                        // reset for next graph replay
        }
    }
}

extern "C" void kernel_launch(void* const* d_in, const int* in_sizes, int n_in,
                              void* d_out, int out_size)
{
    const float* pred       = (const float*)d_in[0];  // (B,T,U+1,V) fp32
    const int*   target     = (const int*)  d_in[1];  // (B,U)
    const int*   pred_len   = (const int*)  d_in[2];  // (B,)
    const int*   target_len = (const int*)  d_in[3];  // (B,)
    float*       out        = (float*)d_out;

    // Kernel 1: logsumexp + paired diagonal scatter + padding. 8 warps/block.
    const int n_rows = Bz * Tz * U1;                        // 133120 rows
    const int blocks = (n_rows + 7) / 8;
    lse_kernel<<<blocks, 256>>>(pred, target, pred_len);

    // Kernel 2: wavefront DP + fused mean.
    const int smem_bytes = NDC * (int)sizeof(float2);       // 168960 B
    cudaFuncSetAttribute(dp_kernel, cudaFuncAttributeMaxDynamicSharedMemorySize,
                         smem_bytes);
    dp_kernel<<<Bz, 256, smem_bytes>>>(target_len, out);
}

// round 10
// speedup vs baseline: 1.0141x; 1.0141x over previous
#include <cuda_runtime.h>
#include <cstddef>
#include <cstdint>

#define Bz 8
#define Tz 256
#define Uz 64
#define U1 65
#define CSTRIDE 66    // paired-row stride in float2 (528 B = 33*16 -> aligned rows)
#define Vz 512
#define ND  320       // diagonal rows: s in [0, 319]
#define NDC (ND * CSTRIDE)   // 21120 float2 per batch
#define NEG 1e30f

#define CH_ROWS  160
#define CH_BYTES (CH_ROWS * CSTRIDE * 8)     // 84480 bytes per chunk

#define LOG2E 1.4426950408889634f
#define LN2   0.6931471805599453f

// Scratch (device globals: allocation inside kernel_launch is forbidden)
// Paired diagonal layout: slot (s,c) = { blank2[s-c][c] , emit2[s-c+1][c-1] },
// i.e. exactly the two operands consumed by dp step d = s+1 at column c.
// Identity padding (x=0, y=-1e30) is written by lse_kernel's spare rows.
__device__ __align__(16) float2 g_pd[Bz * NDC];
__device__ float    g_fb[Bz * U1];      // true blank2[t_last][u] (for final loss)
__device__ float    g_e0[Bz * Uz];      // true emit2[0][u] (row-0 cumsum)
__device__ float    g_loss[Bz];
__device__ unsigned g_done = 0;

__device__ __forceinline__ float ex2f(float x) {
    float r; asm("ex2.approx.ftz.f32 %0, %1;" : "=f"(r) : "f"(x)); return r;
}

// logaddexp in log2 domain: max(x,y) + log2(1 + 2^-|x-y|), Estrin poly.
// Exact at z=0 -> logadd2(x, -1e30) == x (identity), which the padding relies on.
__device__ __forceinline__ float logadd2(float x, float y)
{
    const float m  = fmaxf(x, y);
    const float z  = ex2f(-fabsf(x - y));
    const float z2 = z * z;
    const float t1 = fmaf(-0.6701403f, z, 1.4362632f);
    const float t2 = fmaf(-0.0791604f, z, 0.3126861f);
    const float p  = fmaf(z2, t2, t1);
    return fmaf(z, p, m);
}

// ---------------------------------------------------------------------------
// Kernel 1: per-row logsumexp over V=512 (one warp per (b,t,u) row, HBM-bound).
// Writes blank/emit directly into the paired diagonal layout, with length
// masking baked in, AND writes the identity padding from spare rows.
// ---------------------------------------------------------------------------
__global__ void __launch_bounds__(256) lse_kernel(const float* __restrict__ pred,
                                                  const int* __restrict__ target,
                                                  const int* __restrict__ pred_len)
{
    const int warp = (blockIdx.x * blockDim.x + threadIdx.x) >> 5;
    const int lane = threadIdx.x & 31;
    const int n_rows = Bz * Tz * U1;
    if (warp >= n_rows) return;

    const float* row = pred + (size_t)warp * Vz;

    float4 v[4];
    float mx = -1e30f;
#pragma unroll
    for (int c = 0; c < 4; c++) {
        v[c] = *reinterpret_cast<const float4*>(row + c * 128 + lane * 4);
        mx = fmaxf(mx, fmaxf(fmaxf(v[c].x, v[c].y), fmaxf(v[c].z, v[c].w)));
    }
#pragma unroll
    for (int o = 16; o > 0; o >>= 1)
        mx = fmaxf(mx, __shfl_xor_sync(0xFFFFFFFFu, mx, o));

    float s = 0.0f;
#pragma unroll
    for (int c = 0; c < 4; c++) {
        s += __expf(v[c].x - mx) + __expf(v[c].y - mx)
           + __expf(v[c].z - mx) + __expf(v[c].w - mx);
    }
#pragma unroll
    for (int o = 16; o > 0; o >>= 1)
        s += __shfl_xor_sync(0xFFFFFFFFu, s, o);

    const float lse = mx + __logf(s);

    if (lane == 0) {
        const int b   = warp / (Tz * U1);
        const int r   = warp % (Tz * U1);       // per-batch row id, 0..16639
        const int t   = r / U1;
        const int u   = r % U1;
        const int plen   = pred_len[b];
        const int t_last = plen - 1;
        float2* pd = g_pd + b * NDC;

        // ---- valid writes ----
        const float vb = (row[0] - lse) * LOG2E;              // blank_id = 0
        pd[(t + u) * CSTRIDE + u].x = (t >= t_last) ? 0.0f : vb;
        if (t == t_last) g_fb[b * U1 + u] = vb;               // true value for loss

        if (u < Uz) {
            const int tgt = target[b * Uz + u];
            const float ve = (row[tgt] - lse) * LOG2E;
            pd[(t + u) * CSTRIDE + (u + 1)].y =
                (t < 1 || t >= plen) ? -NEG : ve;
            if (t == 0) g_e0[b * Uz + u] = ve;                // row-0 cumsum input
        }

        // ---- identity padding (spare work, hidden under DRAM stream) ----
        if (r < 4160) {
            const int up = r >> 6, k = r & 63;
            const int d = (k < up) ? k : 256 + k;
            pd[d * CSTRIDE + up].x = 0.0f;
        } else if (r < 8256) {
            const int q = r - 4160;
            const int c = 1 + (q >> 6), k = q & 63;
            const int d = (k < c - 1) ? k : 256 + k;
            pd[d * CSTRIDE + c].y = -NEG;
        } else if (r < 8576) {
            const int d = r - 8256;
            pd[d * CSTRIDE].y = -NEG;
        }
    }
}

// ---------------------------------------------------------------------------
// Kernel 2: alpha DP, 32 threads/CTA. Staging via cp.async.bulk (TMA DMA) in
// two pipelined chunks; row-0 warp-scan runs under the copy; loop waits only
// on chunk 0, chunk 1 lands under the first 160 steps.
// ---------------------------------------------------------------------------
__global__ void __launch_bounds__(32) dp_kernel(const int* __restrict__ target_len,
                                                float* __restrict__ out)
{
    const int b    = blockIdx.x;
    const int lane = threadIdx.x;
    const unsigned FULL = 0xFFFFFFFFu;

    extern __shared__ __align__(16) float2 s_pd[];   // NDC float2 (169 KB)
    __shared__ __align__(8) unsigned long long mbar[2];

    // ---- Issue both bulk copies from lane 0 ----
    const unsigned mb0 = (unsigned)__cvta_generic_to_shared(&mbar[0]);
    const unsigned mb1 = (unsigned)__cvta_generic_to_shared(&mbar[1]);
    if (lane == 0) {
        asm volatile("mbarrier.init.shared.b64 [%0], 1;" :: "r"(mb0) : "memory");
        asm volatile("mbarrier.init.shared.b64 [%0], 1;" :: "r"(mb1) : "memory");
        asm volatile("fence.proxy.async.shared::cta;" ::: "memory");
        const unsigned long long src =
            (unsigned long long)__cvta_generic_to_global(g_pd + b * NDC);
        const unsigned dst = (unsigned)__cvta_generic_to_shared(s_pd);
        asm volatile("mbarrier.arrive.expect_tx.shared.b64 _, [%0], %1;"
                     :: "r"(mb0), "r"((unsigned)CH_BYTES) : "memory");
        asm volatile("cp.async.bulk.shared::cta.global.mbarrier::complete_tx::bytes"
                     " [%0], [%1], %2, [%3];"
                     :: "r"(dst), "l"(src), "r"((unsigned)CH_BYTES), "r"(mb0)
                     : "memory");
        asm volatile("mbarrier.arrive.expect_tx.shared.b64 _, [%0], %1;"
                     :: "r"(mb1), "r"((unsigned)CH_BYTES) : "memory");
        asm volatile("cp.async.bulk.shared::cta.global.mbarrier::complete_tx::bytes"
                     " [%0], [%1], %2, [%3];"
                     :: "r"(dst + CH_BYTES), "l"(src + CH_BYTES),
                        "r"((unsigned)CH_BYTES), "r"(mb1)
                     : "memory");
    }
    __syncwarp();

    const int tlen = target_len[b];   // [56, 64]

    // ---- Row 0 init via warp-scan cumsum of emit[0][.] (under the copy) ----
    const float e0a = __ldg(&g_e0[b * Uz + 2 * lane]);
    const float e0b = __ldg(&g_e0[b * Uz + 2 * lane + 1]);
    const float pair = e0a + e0b;
    float scan = pair;
#pragma unroll
    for (int o = 1; o < 32; o <<= 1) {
        const float n = __shfl_up_sync(FULL, scan, o);
        scan += (lane >= o) ? n : 0.0f;
    }
    float A_e = scan - pair;                   // alpha[0][2l]
    float A_o = A_e + e0a;                     // alpha[0][2l+1]
    float A_t = __shfl_sync(FULL, scan, 31);   // alpha[0][64], uniform

    // ---- Wait for chunk 0 (rows 0..159) ----
    {
        unsigned done = 0;
        while (!done)
            asm volatile("{.reg .pred p; "
                         "mbarrier.try_wait.parity.acquire.cta.shared::cta.b64 p,[%1],%2,0x989680; "
                         "selp.b32 %0,1,0,p;}"
                         : "=r"(done) : "r"(mb0), "r"(0u) : "memory");
    }

    // ---- Main loop: 319 identical, unguarded steps (split at the chunk seam) ----
    const float2* rp = s_pd + 2 * lane;        // this lane's pair base (cols 2l,2l+1)
    const float2* tp = s_pd + Uz;              // col-64 broadcast base

#define DP_STEP                                                           \
    {                                                                     \
        const float prev_o = __shfl_up_sync(FULL, A_o, 1);                \
        const float o31    = __shfl_sync(FULL, A_o, 31);                  \
        const float4 pv = *reinterpret_cast<const float4*>(rp);           \
        const float2 tv = *tp;                                            \
        const float xe = A_e + pv.x;                                      \
        const float ye = prev_o + pv.y;                                   \
        const float xo = A_o + pv.z;                                      \
        const float yo = A_e + pv.w;                                      \
        const float xt = A_t + tv.x;                                      \
        const float yt = o31 + tv.y;                                      \
        A_e = logadd2(xe, ye);                                            \
        A_o = logadd2(xo, yo);                                            \
        A_t = logadd2(xt, yt);                                            \
        rp += CSTRIDE;                                                    \
        tp += CSTRIDE;                                                    \
    }

#pragma unroll 4
    for (int d = 1; d <= CH_ROWS; d++)         // reads rows 0..159
        DP_STEP

    // ---- Wait for chunk 1 (long since landed under ~160 steps) ----
    {
        unsigned done = 0;
        while (!done)
            asm volatile("{.reg .pred p; "
                         "mbarrier.try_wait.parity.acquire.cta.shared::cta.b64 p,[%1],%2,0x989680; "
                         "selp.b32 %0,1,0,p;}"
                         : "=r"(done) : "r"(mb1), "r"(0u) : "memory");
    }

#pragma unroll 4
    for (int d = CH_ROWS + 1; d < ND; d++)     // reads rows 160..318
        DP_STEP
#undef DP_STEP

    // ---- Extract alpha[t_last][tlen] (updates past t_last were frozen) ----
    const int sel = (tlen >> 1) & 31;
    const float vE = __shfl_sync(FULL, A_e, sel);
    const float vO = __shfl_sync(FULL, A_o, sel);
    const float fa = (tlen == Uz) ? A_t : ((tlen & 1) ? vO : vE);

    if (lane == 0) {
        const float fb = __ldg(&g_fb[b * U1 + tlen]);        // true blank2[t_last][tlen]
        g_loss[b] = fa + fb;                                 // log2 domain
        __threadfence();
        const unsigned n = atomicAdd(&g_done, 1);
        if (n == Bz - 1) {
            __threadfence();
            float s = 0.0f;
#pragma unroll
            for (int i = 0; i < Bz; i++)
                s += ((volatile float*)g_loss)[i];
            out[0] = -s * (LN2 / Bz);
            g_done = 0;                        // reset for next graph replay
        }
    }
}

extern "C" void kernel_launch(void* const* d_in, const int* in_sizes, int n_in,
                              void* d_out, int out_size)
{
    const float* pred       = (const float*)d_in[0];  // (B,T,U+1,V) fp32
    const int*   target     = (const int*)  d_in[1];  // (B,U)
    const int*   pred_len   = (const int*)  d_in[2];  // (B,)
    const int*   target_len = (const int*)  d_in[3];  // (B,)
    float*       out        = (float*)d_out;

    // Kernel 1: logsumexp + paired diagonal scatter + padding. 8 warps/block.
    const int n_rows = Bz * Tz * U1;                        // 133120 rows
    const int blocks = (n_rows + 7) / 8;
    lse_kernel<<<blocks, 256>>>(pred, target, pred_len);

    // Kernel 2: wavefront DP + fused mean. 32 threads/CTA, TMA staging.
    const int smem_bytes = NDC * (int)sizeof(float2);       // 168960 B
    cudaFuncSetAttribute(dp_kernel, cudaFuncAttributeMaxDynamicSharedMemorySize,
                         smem_bytes);
    dp_kernel<<<Bz, 32, smem_bytes>>>(target_len, out);
}